// round 6
// baseline (speedup 1.0000x reference)
#include <cuda_runtime.h>
#include <cuda_bf16.h>
#include <cstdint>

// ============================================================================
// MajFC:  out = 1.125 * <X", W">  with augmented ±1 vectors (K = 3072 + 1024):
//   per 3-group, clip(sum,-1,1) = 0.5*(x0w0 + x1w1 + x2w2 - (x0x1x2)(w0w1w2)).
// Bit-packed:  out = 4608 - 2.25 * popc(xbits ^ wbits)  over 128 words.
// GEMM is K-split 4 ways for occupancy; exact int partials are combined after.
// ============================================================================

#define BROWS 256
#define CIN   3072
#define COUT  1024
#define KW    128            // 4096 bits per row
#define NSPLIT 4
#define KC    (KW / NSPLIT)  // 32 words per split

__device__ __align__(16) uint32_t g_Xb[BROWS * KW];              // 128 KB
__device__ __align__(16) uint32_t g_Wb[COUT  * KW];              // 512 KB
__device__ __align__(16) int      g_part[NSPLIT * BROWS * COUT]; // 4 MB

// ---------------------------------------------------------------------------
// Unified single-pass pack. One warp = one 96-float segment (32 groups of 3).
// ---------------------------------------------------------------------------
#define XSEGS (BROWS * 32)           // 8192 warps
#define WSEGS (COUT  * 32)           // 32768 warps
#define PACK_WARPS (XSEGS + WSEGS)   // 40960

__global__ void pack_kernel(const float* __restrict__ x,
                            const float* __restrict__ w) {
    int gw   = (blockIdx.x * blockDim.x + threadIdx.x) >> 5;
    int lane = threadIdx.x & 31;

    const float* src;
    uint32_t*    dst;
    unsigned flip;
    int seg;
    if (gw < XSEGS) {
        int row = gw >> 5; seg = gw & 31;
        src = x + (size_t)row * CIN;
        dst = g_Xb + (size_t)row * KW;
        flip = 0u;
    } else {
        int u = gw - XSEGS;
        int row = u >> 5; seg = u & 31;
        src = w + (size_t)row * CIN;
        dst = g_Wb + (size_t)row * KW;
        flip = 1u;                      // -prod(W) folded into the bit
    }

    const float* p = src + seg * 96 + lane * 3;
    unsigned b0 = p[0] > 0.f;
    unsigned b1 = p[1] > 0.f;
    unsigned b2 = p[2] > 0.f;
    unsigned w0 = __ballot_sync(0xFFFFFFFFu, b0);
    unsigned w1 = __ballot_sync(0xFFFFFFFFu, b1);
    unsigned w2 = __ballot_sync(0xFFFFFFFFu, b2);
    unsigned wp = __ballot_sync(0xFFFFFFFFu, b0 ^ b1 ^ b2 ^ flip);

    if (lane == 0) {
        dst[seg * 3 + 0] = w0;
        dst[seg * 3 + 1] = w1;
        dst[seg * 3 + 2] = w2;
        dst[96 + seg]    = wp;
    }
}

// ---------------------------------------------------------------------------
// Binary GEMM, K-split: CTA tile 32(m) x 16(n) over one 32-word K chunk.
// 128 threads, thread tile 2x2. grid = (64, 8, 4) = 2048 CTAs.
// Pitch 36 words = 144 B: EVERY row base (144*row) is 16B-aligned -> LDS.128
// legal for both even and odd rows (R5 bug: pitch 34 left odd rows 8B-aligned).
// Conflicts: X-reads broadcast per phase; W-reads 2-way (unavoidable, ~2cyc).
// ---------------------------------------------------------------------------
#define GM 32
#define GN 16
#define SP 36

__global__ void __launch_bounds__(128, 10) maj_gemm_kernel() {
    __shared__ __align__(16) uint32_t Xs[GM][SP];   // 4.5 KB
    __shared__ __align__(16) uint32_t Ws[GN][SP];   // 2.25 KB

    int tid = threadIdx.x;
    int n0 = blockIdx.x * GN;         // 64
    int m0 = blockIdx.y * GM;         // 8
    int sp = blockIdx.z;              // 4
    int k0 = sp * KC;

    // Stage: 48 rows x 32 words = 384 uint4, 3 per thread. STS.128 (16B ok).
#pragma unroll
    for (int p = 0; p < 3; p++) {
        int idx = p * 128 + tid;
        int row = idx >> 3, c = (idx & 7) << 2;
        const uint32_t* src = (row < GM)
            ? &g_Xb[(size_t)(m0 + row) * KW + k0 + c]
            : &g_Wb[(size_t)(n0 + row - GM) * KW + k0 + c];
        uint4 v = *reinterpret_cast<const uint4*>(src);
        uint32_t* d = (row < GM) ? &Xs[row][c] : &Ws[row - GM][c];
        *reinterpret_cast<uint4*>(d) = v;
    }
    __syncthreads();

    int mi = tid >> 3;                // 0..15 -> m rows 2mi, 2mi+1
    int ni = tid & 7;                 // 0..7  -> n rows 2ni, 2ni+1
    const uint32_t* xa = &Xs[mi * 2][0];
    const uint32_t* xb = &Xs[mi * 2 + 1][0];
    const uint32_t* wa = &Ws[ni * 2][0];
    const uint32_t* wb = &Ws[ni * 2 + 1][0];

    int a00 = 0, a01 = 0, a10 = 0, a11 = 0;
#pragma unroll
    for (int k = 0; k < KC; k += 4) {
        uint4 x0 = *reinterpret_cast<const uint4*>(&xa[k]);
        uint4 x1 = *reinterpret_cast<const uint4*>(&xb[k]);
        uint4 v0 = *reinterpret_cast<const uint4*>(&wa[k]);
        uint4 v1 = *reinterpret_cast<const uint4*>(&wb[k]);
        a00 += __popc(x0.x ^ v0.x) + __popc(x0.y ^ v0.y)
             + __popc(x0.z ^ v0.z) + __popc(x0.w ^ v0.w);
        a01 += __popc(x0.x ^ v1.x) + __popc(x0.y ^ v1.y)
             + __popc(x0.z ^ v1.z) + __popc(x0.w ^ v1.w);
        a10 += __popc(x1.x ^ v0.x) + __popc(x1.y ^ v0.y)
             + __popc(x1.z ^ v0.z) + __popc(x1.w ^ v0.w);
        a11 += __popc(x1.x ^ v1.x) + __popc(x1.y ^ v1.y)
             + __popc(x1.z ^ v1.z) + __popc(x1.w ^ v1.w);
    }

    int m = m0 + mi * 2, n = n0 + ni * 2;
    int* pb = g_part + (size_t)sp * (BROWS * COUT) + (size_t)m * COUT + n;
    *reinterpret_cast<int2*>(pb)        = make_int2(a00, a01);
    *reinterpret_cast<int2*>(pb + COUT) = make_int2(a10, a11);
}

// ---------------------------------------------------------------------------
// Combine: out = 4608 - 2.25 * (p0+p1+p2+p3), int4-vectorized.
// ---------------------------------------------------------------------------
__global__ void combine_kernel(float* __restrict__ out) {
    int i = (blockIdx.x * blockDim.x + threadIdx.x) << 2;
    const int NPO = BROWS * COUT;
    int4 a = *reinterpret_cast<const int4*>(&g_part[i]);
    int4 b = *reinterpret_cast<const int4*>(&g_part[NPO + i]);
    int4 c = *reinterpret_cast<const int4*>(&g_part[2 * NPO + i]);
    int4 d = *reinterpret_cast<const int4*>(&g_part[3 * NPO + i]);
    float4 o;
    o.x = 4608.0f - 2.25f * (float)(a.x + b.x + c.x + d.x);
    o.y = 4608.0f - 2.25f * (float)(a.y + b.y + c.y + d.y);
    o.z = 4608.0f - 2.25f * (float)(a.z + b.z + c.z + d.z);
    o.w = 4608.0f - 2.25f * (float)(a.w + b.w + c.w + d.w);
    *reinterpret_cast<float4*>(&out[i]) = o;
}

// ---------------------------------------------------------------------------
extern "C" void kernel_launch(void* const* d_in, const int* in_sizes, int n_in,
                              void* d_out, int out_size) {
    const float* x = (const float*)d_in[0];   // [256, 3072]
    const float* w = (const float*)d_in[1];   // [1024, 3072]
    float* out = (float*)d_out;               // [256, 1024] float32

    pack_kernel<<<PACK_WARPS * 32 / 256, 256>>>(x, w);

    dim3 grid(COUT / GN, BROWS / GM, NSPLIT); // (64, 8, 4) = 2048 CTAs
    maj_gemm_kernel<<<grid, 128>>>();

    combine_kernel<<<BROWS * COUT / (256 * 4), 256>>>(out);
}